// round 16
// baseline (speedup 1.0000x reference)
#include <cuda_runtime.h>
#include <cuda_fp16.h>
#include <cstdint>

#define MAXN  50000
#define MAXNP 50048          // padded to tile multiple (OOB-safe zero stores)
#define MAXE  1600000
#define FIN   48
#define HID   32
#define NCLS  10
#define KS    4

// ---------------- scratch (device globals; padded) --------------------------------
__device__ __half    g_xw1h[MAXNP * KS * HID];  // [N][4][32] fp16
__device__ float     g_rb1 [MAXNP * HID];       // x@root1 + bias1 (fp32)
__device__ __align__(16) __half g_xw2h[MAXNP * 64];  // [N][4][16] fp16 (10 used per k)
__device__ float     g_rb2 [MAXNP * NCLS];
__device__ __align__(16) __half g_agg1h[MAXNP * HID];
__device__ __align__(16) __half g_agg2h[MAXNP * 16]; // [N][16] (10 used)
__device__ float     g_deg [MAXNP];
__device__ uint2     g_pack[MAXE];              // x: src|dst<<16,  y: frac-bits|k0
__device__ __half    g_wt1h[160 * FIN];         // W1^T+root1^T fp16 [160][48]
__device__ __half    g_wt2h[56 * HID];          // W2^T+root2^T fp16 [56][32]
__device__ int       g_is64;

// ---------------- helpers ---------------------------------------------------------
__device__ __forceinline__ void red_add_v4h2(__half* addr, uint4 v) {
    asm volatile("red.global.add.noftz.v4.f16x2 [%0], {%1,%2,%3,%4};"
                 :: "l"(addr), "r"(v.x), "r"(v.y), "r"(v.z), "r"(v.w) : "memory");
}
__device__ __forceinline__ void red_add_h2(__half* addr, unsigned v) {
    asm volatile("red.global.add.noftz.f16x2 [%0], %1;"
                 :: "l"(addr), "r"(v) : "memory");
}
__device__ __forceinline__ void mma16816(float* d, const unsigned* a,
                                         unsigned b0, unsigned b1) {
    asm("mma.sync.aligned.m16n8k16.row.col.f32.f16.f16.f32 "
        "{%0,%1,%2,%3}, {%4,%5,%6,%7}, {%8,%9}, {%0,%1,%2,%3};"
        : "+f"(d[0]), "+f"(d[1]), "+f"(d[2]), "+f"(d[3])
        : "r"(a[0]), "r"(a[1]), "r"(a[2]), "r"(a[3]), "r"(b0), "r"(b1));
}
__device__ __forceinline__ uint2 enc_edge(int src, int dst, float u) {
    float vv = u * (float)(KS - 1);
    float vf = floorf(vv);
    float frac = vv - vf;
    int k0 = min(max((int)vf, 0), KS - 1);
    return make_uint2((unsigned)src | ((unsigned)dst << 16),
                      (__float_as_uint(frac) & ~3u) | (unsigned)k0);
}

// ---------------- init: detect + wprep (block 0) + deg zero (other blocks) --------
__global__ void k_init(const void* __restrict__ ei,
                       const float* __restrict__ W1, const float* __restrict__ root1,
                       const float* __restrict__ W2, const float* __restrict__ root2,
                       int N) {
    if (blockIdx.x == 0) {
        if (threadIdx.x < 32) {
            int hi = ((const int*)ei)[2 * threadIdx.x + 1];
            unsigned b = __ballot_sync(0xffffffffu, hi != 0);
            if (threadIdx.x == 0) g_is64 = (b == 0) ? 1 : 0;
        }
        for (int i = threadIdx.x; i < 160 * FIN; i += 256) {
            int j = i / FIN, f = i % FIN;
            float v = (j < 128) ? W1[(((j >> 5) * FIN) + f) * HID + (j & 31)]
                                : root1[f * HID + (j - 128)];
            g_wt1h[i] = __float2half(v);
        }
        for (int i = threadIdx.x; i < 56 * HID; i += 256) {
            int c = i / HID, o = i % HID;
            float v = 0.f;
            if (c < 40)      { int k = c / NCLS, cc = c % NCLS; v = W2[(k * HID + o) * NCLS + cc]; }
            else if (c < 50) v = root2[o * NCLS + (c - 40)];
            g_wt2h[i] = __float2half(v);
        }
    } else {
        for (int i = (blockIdx.x - 1) * 256 + threadIdx.x; i < MAXNP;
             i += (gridDim.x - 1) * 256)
            g_deg[i] = 0.f;
    }
}

// ---------------- fused: xw1 HMMA + agg1h zero (blocks < xwblocks) + edge pack ----
__global__ void __launch_bounds__(256) k_main1(const float* __restrict__ x,
                                               const float* __restrict__ bias1,
                                               const void* __restrict__ ei,
                                               const float* __restrict__ ea,
                                               int N, int E, int xwblocks) {
    __shared__ __align__(16) __half xs[128 * 56];   // 14336 B
    __shared__ __align__(16) __half wt[160 * 56];   // 17920 B
    __shared__ float bsh[HID];
    const int tid = threadIdx.x;

    if (blockIdx.x >= xwblocks) {
        int b = blockIdx.x - xwblocks;
        long long e0 = ((long long)b * 256 + tid) * 2;
        if (e0 >= E) return;
        bool vec = ((E & 1) == 0) && (e0 + 1 < E);
        if (vec) {
            int src0, dst0, src1, dst1;
            if (g_is64) {
                longlong2 s = *(const longlong2*)((const long long*)ei + e0);
                longlong2 d = *(const longlong2*)((const long long*)ei + E + e0);
                src0 = (int)s.x; src1 = (int)s.y; dst0 = (int)d.x; dst1 = (int)d.y;
            } else {
                int2 s = *(const int2*)((const int*)ei + e0);
                int2 d = *(const int2*)((const int*)ei + E + e0);
                src0 = s.x; src1 = s.y; dst0 = d.x; dst1 = d.y;
            }
            float2 u = *(const float2*)(ea + e0);
            uint2 r0 = enc_edge(src0, dst0, u.x);
            uint2 r1 = enc_edge(src1, dst1, u.y);
            *(uint4*)&g_pack[e0] = make_uint4(r0.x, r0.y, r1.x, r1.y);
            atomicAdd(&g_deg[dst0], 1.0f);
            atomicAdd(&g_deg[dst1], 1.0f);
        } else {
            for (long long e = e0; e < e0 + 2 && e < E; e++) {
                int src, dst;
                if (g_is64) {
                    src = (int)((const long long*)ei)[e];
                    dst = (int)((const long long*)ei)[E + e];
                } else {
                    src = ((const int*)ei)[e];
                    dst = ((const int*)ei)[E + e];
                }
                g_pack[e] = enc_edge(src, dst, ea[e]);
                atomicAdd(&g_deg[dst], 1.0f);
            }
        }
        return;
    }

    // zero this block's 128-node slice of agg1h (8KB; in-bounds via MAXNP padding)
    int nbase = blockIdx.x * 128;
    {
        uint4 z = make_uint4(0, 0, 0, 0);
        uint4* dst = (uint4*)&g_agg1h[nbase * HID];   // 512 uint4
        for (int i = tid; i < 512; i += 256) dst[i] = z;
    }

    // xw1 HMMA
    for (int i2 = tid; i2 < 160 * (FIN / 2); i2 += 256) {
        int j = i2 / (FIN / 2), fp = i2 % (FIN / 2);
        *(__half2*)&wt[j * 56 + fp * 2] = ((const __half2*)g_wt1h)[i2];
    }
    if (tid < HID) bsh[tid] = bias1[tid];
    for (int i = tid; i < 128 * (FIN / 2); i += 256) {
        int nn = i / (FIN / 2), fp = i % (FIN / 2);
        int n = nbase + nn;
        float2 v = (n < N) ? *(const float2*)&x[(long long)n * FIN + fp * 2]
                           : make_float2(0.f, 0.f);
        *(__half2*)&xs[nn * 56 + fp * 2] = __floats2half2_rn(v.x, v.y);
    }
    __syncthreads();

    const int warp = tid >> 5;
    const int lane = tid & 31;
    const int g = lane >> 2;
    const int t = lane & 3;
    const int wn = warp * 16;

    unsigned a[3][4];
    #pragma unroll
    for (int kc = 0; kc < 3; kc++) {
        int k0 = kc * 16;
        a[kc][0] = *(const unsigned*)&xs[(wn + g)     * 56 + k0 + 2 * t];
        a[kc][1] = *(const unsigned*)&xs[(wn + g + 8) * 56 + k0 + 2 * t];
        a[kc][2] = *(const unsigned*)&xs[(wn + g)     * 56 + k0 + 2 * t + 8];
        a[kc][3] = *(const unsigned*)&xs[(wn + g + 8) * 56 + k0 + 2 * t + 8];
    }
    int node0 = nbase + wn + g;
    int node1 = node0 + 8;
    #pragma unroll
    for (int nt = 0; nt < 20; nt++) {
        int n0 = nt * 8;
        float d[4] = {0.f, 0.f, 0.f, 0.f};
        #pragma unroll
        for (int kc = 0; kc < 3; kc++) {
            unsigned b0 = *(const unsigned*)&wt[(n0 + g) * 56 + kc * 16 + 2 * t];
            unsigned b1 = *(const unsigned*)&wt[(n0 + g) * 56 + kc * 16 + 2 * t + 8];
            mma16816(d, a[kc], b0, b1);
        }
        int col = n0 + 2 * t;
        if (col < 128) {
            if (node0 < N) *(__half2*)&g_xw1h[node0 * 128 + col] = __floats2half2_rn(d[0], d[1]);
            if (node1 < N) *(__half2*)&g_xw1h[node1 * 128 + col] = __floats2half2_rn(d[2], d[3]);
        } else {
            int o = col - 128;
            float b0f = bsh[o], b1f = bsh[o + 1];
            if (node0 < N) *(float2*)&g_rb1[node0 * HID + o] = make_float2(d[0] + b0f, d[1] + b1f);
            if (node1 < N) *(float2*)&g_rb1[node1 * HID + o] = make_float2(d[2] + b0f, d[3] + b1f);
        }
    }
}

// ---------------- layer-1 edge scatter: 4 lanes/edge, uint4 gather, f16x2 red -----
__global__ void __launch_bounds__(256) k_edge1(int E) {
    long long t = (long long)blockIdx.x * blockDim.x + threadIdx.x;
    long long e = t >> 2;
    int j = (int)(t & 3);           // 8 features per lane
    if (e >= E) return;
    uint2 r = g_pack[e];
    int src = r.x & 0xffff;
    int dst = r.x >> 16;
    int k0  = r.y & 3;
    int k1  = min(k0 + 1, KS - 1);
    float f = __uint_as_float(r.y & ~3u);
    const __half* base = g_xw1h + src * 128;
    uint4 pa = *(const uint4*)(base + k0 * 32 + j * 8);
    uint4 pb = *(const uint4*)(base + k1 * 32 + j * 8);
    float w0 = 1.0f - f;
    uint4 o;
    #pragma unroll
    for (int q = 0; q < 4; q++) {
        float2 A = __half22float2(((const __half2*)&pa)[q]);
        float2 B = __half22float2(((const __half2*)&pb)[q]);
        __half2 h = __floats2half2_rn(w0 * A.x + f * B.x, w0 * A.y + f * B.y);
        ((__half2*)&o)[q] = h;
    }
    red_add_v4h2(g_agg1h + dst * HID + j * 8, o);
}

// ---------------- layer-2 node GEMM (64-node tiles, 256 thr) + ELU + agg2h zero ----
__global__ void __launch_bounds__(256) k_prep2(const float* __restrict__ bias2, int N) {
    __shared__ __align__(16) __half hs[64 * 40];    // 5120 B
    __shared__ __align__(16) __half wt[56 * 40];    // 4480 B
    __shared__ float bsh[NCLS];
    const int tid = threadIdx.x;
    int nbase = blockIdx.x * 64;
    // zero this block's agg2h slice (64 nodes * 8 words; in-bounds via padding)
    {
        uint4 z = make_uint4(0, 0, 0, 0);
        uint4* dst = (uint4*)&g_agg2h[nbase * 16];   // 128 uint4
        for (int i = tid; i < 128; i += 256) dst[i] = z;
    }
    for (int i2 = tid; i2 < 56 * (HID / 2); i2 += 256) {
        int c = i2 / (HID / 2), op = i2 % (HID / 2);
        *(__half2*)&wt[c * 40 + op * 2] = ((const __half2*)g_wt2h)[i2];
    }
    if (tid < NCLS) bsh[tid] = bias2[tid];
    for (int i = tid; i < 64 * (HID / 4); i += 256) {
        int nn = i / (HID / 4), q = i % (HID / 4);
        int n = nbase + nn;
        float4 h4 = make_float4(0.f, 0.f, 0.f, 0.f);
        if (n < N) {
            float inv = 1.0f / fmaxf(g_deg[n], 1.0f);
            uint2 ah = *(const uint2*)&g_agg1h[n * HID + q * 4];
            float2 a01 = __half22float2(*(const __half2*)&ah.x);
            float2 a23 = __half22float2(*(const __half2*)&ah.y);
            float4 rb = *(const float4*)&g_rb1[n * HID + q * 4];
            float v0 = a01.x * inv + rb.x, v1 = a01.y * inv + rb.y;
            float v2 = a23.x * inv + rb.z, v3 = a23.y * inv + rb.w;
            h4.x = (v0 > 0.f) ? v0 : expm1f(v0);
            h4.y = (v1 > 0.f) ? v1 : expm1f(v1);
            h4.z = (v2 > 0.f) ? v2 : expm1f(v2);
            h4.w = (v3 > 0.f) ? v3 : expm1f(v3);
        }
        *(__half2*)&hs[nn * 40 + q * 4]     = __floats2half2_rn(h4.x, h4.y);
        *(__half2*)&hs[nn * 40 + q * 4 + 2] = __floats2half2_rn(h4.z, h4.w);
    }
    __syncthreads();

    const int warp = tid >> 5;
    if (warp >= 4) return;          // 4 MMA warps cover 64 nodes
    const int lane = tid & 31;
    const int g = lane >> 2;
    const int t = lane & 3;
    const int wn = warp * 16;

    unsigned a[2][4];
    #pragma unroll
    for (int kc = 0; kc < 2; kc++) {
        int k0 = kc * 16;
        a[kc][0] = *(const unsigned*)&hs[(wn + g)     * 40 + k0 + 2 * t];
        a[kc][1] = *(const unsigned*)&hs[(wn + g + 8) * 40 + k0 + 2 * t];
        a[kc][2] = *(const unsigned*)&hs[(wn + g)     * 40 + k0 + 2 * t + 8];
        a[kc][3] = *(const unsigned*)&hs[(wn + g + 8) * 40 + k0 + 2 * t + 8];
    }
    int node0 = nbase + wn + g;
    int node1 = node0 + 8;
    #pragma unroll
    for (int nt = 0; nt < 7; nt++) {
        int n0 = nt * 8;
        float d[4] = {0.f, 0.f, 0.f, 0.f};
        #pragma unroll
        for (int kc = 0; kc < 2; kc++) {
            unsigned b0 = *(const unsigned*)&wt[(n0 + g) * 40 + kc * 16 + 2 * t];
            unsigned b1 = *(const unsigned*)&wt[(n0 + g) * 40 + kc * 16 + 2 * t + 8];
            mma16816(d, a[kc], b0, b1);
        }
        int col = n0 + 2 * t;
        if (col < 40) {
            int k = col / 10, c = col - k * 10;        // pairs never cross k boundary
            if (node0 < N) *(__half2*)&g_xw2h[node0 * 64 + k * 16 + c] = __floats2half2_rn(d[0], d[1]);
            if (node1 < N) *(__half2*)&g_xw2h[node1 * 64 + k * 16 + c] = __floats2half2_rn(d[2], d[3]);
        } else if (col < 50) {
            int o = col - 40;
            float b0f = bsh[o], b1f = bsh[o + 1];
            if (node0 < N) *(float2*)&g_rb2[node0 * NCLS + o] = make_float2(d[0] + b0f, d[1] + b1f);
            if (node1 < N) *(float2*)&g_rb2[node1 * NCLS + o] = make_float2(d[2] + b0f, d[3] + b1f);
        }
    }
}

// ---------------- layer-2 edge scatter: 1 thread/edge, wide loads, 2 REDs ---------
__global__ void __launch_bounds__(256) k_edge2(int E) {
    long long e = (long long)blockIdx.x * blockDim.x + threadIdx.x;
    if (e >= E) return;
    uint2 r = g_pack[e];
    int src = r.x & 0xffff;
    int dst = r.x >> 16;
    int k0  = r.y & 3;
    int k1  = min(k0 + 1, KS - 1);
    float f = __uint_as_float(r.y & ~3u);
    const __half* base = g_xw2h + src * 64;
    uint4    a0 = *(const uint4*)(base + k0 * 16);          // halfs 0..7 (32B aligned)
    unsigned a1 = *(const unsigned*)(base + k0 * 16 + 8);   // halfs 8,9
    uint4    b0 = *(const uint4*)(base + k1 * 16);
    unsigned b1 = *(const unsigned*)(base + k1 * 16 + 8);
    float w0 = 1.0f - f;
    uint4 o;
    #pragma unroll
    for (int q = 0; q < 4; q++) {
        float2 A = __half22float2(((const __half2*)&a0)[q]);
        float2 B = __half22float2(((const __half2*)&b0)[q]);
        ((__half2*)&o)[q] = __floats2half2_rn(w0 * A.x + f * B.x, w0 * A.y + f * B.y);
    }
    float2 A4 = __half22float2(*(const __half2*)&a1);
    float2 B4 = __half22float2(*(const __half2*)&b1);
    __half2 o4 = __floats2half2_rn(w0 * A4.x + f * B4.x, w0 * A4.y + f * B4.y);
    __half* dsta = g_agg2h + dst * 16;
    red_add_v4h2(dsta, o);
    red_add_h2(dsta + 8, *(unsigned*)&o4);
}

// ---------------- final: mean + root + bias + log_softmax -------------------------
__global__ void k_out(float* __restrict__ out, int N) {
    int n = blockIdx.x * blockDim.x + threadIdx.x;
    if (n >= N) return;
    float inv = 1.0f / fmaxf(g_deg[n], 1.0f);
    float v[NCLS];
    float mx = -1e30f;
    #pragma unroll
    for (int q = 0; q < NCLS / 2; q++) {
        unsigned aw = *(const unsigned*)&g_agg2h[n * 16 + q * 2];
        float2 a  = __half22float2(*(const __half2*)&aw);
        float2 rb = *(const float2*)&g_rb2[n * NCLS + q * 2];
        v[q*2]   = a.x * inv + rb.x;
        v[q*2+1] = a.y * inv + rb.y;
        mx = fmaxf(mx, fmaxf(v[q*2], v[q*2+1]));
    }
    float s = 0.f;
    #pragma unroll
    for (int c = 0; c < NCLS; c++) s += expf(v[c] - mx);
    float ls = logf(s) + mx;
    float2* o2 = (float2*)&out[n * NCLS];
    #pragma unroll
    for (int q = 0; q < NCLS / 2; q++)
        o2[q] = make_float2(v[q*2] - ls, v[q*2+1] - ls);
}

// ---------------- launch -----------------------------------------------------------
extern "C" void kernel_launch(void* const* d_in, const int* in_sizes, int n_in,
                              void* d_out, int out_size) {
    const float* x     = (const float*)d_in[0];
    const void*  ei    =               d_in[1];
    const float* ea    = (const float*)d_in[2];
    const float* W1    = (const float*)d_in[3];
    const float* root1 = (const float*)d_in[4];
    const float* bias1 = (const float*)d_in[5];
    const float* W2    = (const float*)d_in[6];
    const float* root2 = (const float*)d_in[7];
    const float* bias2 = (const float*)d_in[8];
    float* out = (float*)d_out;

    int N = in_sizes[0] / FIN;     // 50000
    int E = in_sizes[2];           // 1600000

    k_init<<<(MAXNP + 255) / 256 + 1, 256>>>(ei, W1, root1, W2, root2, N);
    int xwblocks = (N + 127) / 128;
    int packblocks = (E / 2 + 256) / 256;
    k_main1<<<xwblocks + packblocks, 256>>>(x, bias1, ei, ea, N, E, xwblocks);
    long long th1 = (long long)E * 4;
    k_edge1<<<(int)((th1 + 255) / 256), 256>>>(E);
    k_prep2<<<(N + 63) / 64, 256>>>(bias2, N);
    k_edge2<<<(E + 255) / 256, 256>>>(E);
    k_out<<<(N + 255) / 256, 256>>>(out, N);
}